// round 1
// baseline (speedup 1.0000x reference)
#include <cuda_runtime.h>
#include <math.h>

#define B_ 8
#define S_ 4096
#define D_ 1024
#define R_ 64

// ---------------- scratch (no allocations allowed) ----------------
__device__ __align__(16) float g_xq[B_ * S_ * R_];   // 8 MB: x @ (Q*scale), [B*S][64]
__device__ float g_m[B_ * S_];                        // row max of logits
__device__ float g_inv[B_ * S_];                      // 1 / row sum of exp

// ---------------- packed fp32x2 FMA (Blackwell) ----------------
__device__ __forceinline__ void ffma2(float2 &c, const float2 a, const float2 b) {
    asm("fma.rn.f32x2 %0, %1, %2, %0;"
        : "+l"(*reinterpret_cast<unsigned long long *>(&c))
        : "l"(*reinterpret_cast<const unsigned long long *>(&a)),
          "l"(*reinterpret_cast<const unsigned long long *>(&b)));
}

// ---------------- software exp (avoids MUFU bottleneck) ----------------
// valid for x <= 0 (softmax-shifted logits); ~1e-6 rel err
__device__ __forceinline__ float fexp(float x) {
    x = fmaxf(x, -87.0f);
    float y = x * 1.4426950408889634f;   // log2(e)
    float n = rintf(y);
    float f = y - n;
    float p = 1.3333558e-3f;
    p = fmaf(p, f, 9.6181291e-3f);
    p = fmaf(p, f, 5.5504109e-2f);
    p = fmaf(p, f, 2.4022651e-1f);
    p = fmaf(p, f, 6.9314718e-1f);
    p = fmaf(p, f, 1.0f);
    int e = (int)n;
    return p * __int_as_float((e + 127) << 23);
}

// =====================================================================
// Kernel 1: g_xq[row][r] = scale * sum_d x[row][d] * Q[d][r]
// CTA: 128 rows x 64 cols, 256 threads, thread tile 4m x 8r (4 f32x2)
// =====================================================================
__global__ void __launch_bounds__(256) k_proj(const float *__restrict__ x,
                                              const float *__restrict__ Q) {
    extern __shared__ float sm[];
    float *Xs = sm;              // [128][68]
    float *Qs = sm + 128 * 68;   // [64][68]
    const int t = threadIdx.x;
    const int row0 = blockIdx.x * 128;
    const int ty = t >> 3;  // 0..31 -> m = ty*4+i
    const int tx = t & 7;   // 0..7  -> r = tx*8+j

    float2 acc[4][4];
#pragma unroll
    for (int i = 0; i < 4; i++)
#pragma unroll
        for (int p = 0; p < 4; p++) acc[i][p] = make_float2(0.f, 0.f);

    for (int dc = 0; dc < 16; dc++) {
        const int d0 = dc * 64;
#pragma unroll
        for (int i = 0; i < 8; i++) {  // X tile: 128x64 = 2048 float4
            int f = t + i * 256;
            int r = f >> 4, c4 = f & 15;
            float4 v = *reinterpret_cast<const float4 *>(
                x + (size_t)(row0 + r) * D_ + d0 + c4 * 4);
            *reinterpret_cast<float4 *>(Xs + r * 68 + c4 * 4) = v;
        }
#pragma unroll
        for (int i = 0; i < 4; i++) {  // Q tile: 64x64 = 1024 float4
            int f = t + i * 256;
            int r = f >> 4, c4 = f & 15;
            float4 v = *reinterpret_cast<const float4 *>(
                Q + (size_t)(d0 + r) * R_ + c4 * 4);
            *reinterpret_cast<float4 *>(Qs + r * 68 + c4 * 4) = v;
        }
        __syncthreads();
#pragma unroll 4
        for (int dd = 0; dd < 64; dd++) {
            float2 aa[4];
#pragma unroll
            for (int i = 0; i < 4; i++) {
                float a = Xs[(ty * 4 + i) * 68 + dd];
                aa[i] = make_float2(a, a);
            }
            float4 q0 = *reinterpret_cast<const float4 *>(Qs + dd * 68 + tx * 8);
            float4 q1 = *reinterpret_cast<const float4 *>(Qs + dd * 68 + tx * 8 + 4);
            float2 bb[4] = {make_float2(q0.x, q0.y), make_float2(q0.z, q0.w),
                            make_float2(q1.x, q1.y), make_float2(q1.z, q1.w)};
#pragma unroll
            for (int i = 0; i < 4; i++)
#pragma unroll
                for (int p = 0; p < 4; p++) ffma2(acc[i][p], aa[i], bb[p]);
        }
        __syncthreads();
    }
    const float scale = 0.03125f;  // 1/sqrt(1024)
#pragma unroll
    for (int i = 0; i < 4; i++) {
        float *dst = g_xq + (size_t)(row0 + ty * 4 + i) * R_ + tx * 8;
        float4 o0 = make_float4(acc[i][0].x * scale, acc[i][0].y * scale,
                                acc[i][1].x * scale, acc[i][1].y * scale);
        float4 o1 = make_float4(acc[i][2].x * scale, acc[i][2].y * scale,
                                acc[i][3].x * scale, acc[i][3].y * scale);
        *reinterpret_cast<float4 *>(dst) = o0;
        *reinterpret_cast<float4 *>(dst + 4) = o1;
    }
}

// =====================================================================
// Kernel 2: per-row softmax stats (max, 1/sum) via online reduction.
// CTA: 64 query rows, loop over key tiles of 128; thread tile 4m x 8n.
// =====================================================================
__global__ void __launch_bounds__(256) k_stats() {
    extern __shared__ float sm[];
    float *Qs = sm;                 // [64][68]
    float *Ks = Qs + 64 * 68;       // [64 r][132 n]  (transposed)
    float *redm = Ks + 64 * 132;    // [16][64]
    float *reds = redm + 16 * 64;   // [16][64]
    const int t = threadIdx.x;
    const int ty = t >> 4, tx = t & 15;
    const int bm0 = blockIdx.x * 64;  // global query row base
    const int kbase = (bm0 >> 12) << 12;

#pragma unroll
    for (int i = 0; i < 4; i++) {
        int f = t + i * 256;
        int r = f >> 4, c4 = f & 15;
        float4 v = *reinterpret_cast<const float4 *>(
            g_xq + (size_t)(bm0 + r) * R_ + c4 * 4);
        *reinterpret_cast<float4 *>(Qs + r * 68 + c4 * 4) = v;
    }

    float run_m[4], run_s[4];
#pragma unroll
    for (int i = 0; i < 4; i++) { run_m[i] = -INFINITY; run_s[i] = 0.f; }

    for (int nb = 0; nb < 32; nb++) {
        const int n0 = kbase + nb * 128;
        {  // load K transposed: Ks[r][n]
            int n = t >> 1, rb = (t & 1) * 32;
            const float *src = g_xq + (size_t)(n0 + n) * R_ + rb;
#pragma unroll
            for (int k8 = 0; k8 < 8; k8++) {
                float4 v = *reinterpret_cast<const float4 *>(src + k8 * 4);
                Ks[(rb + k8 * 4 + 0) * 132 + n] = v.x;
                Ks[(rb + k8 * 4 + 1) * 132 + n] = v.y;
                Ks[(rb + k8 * 4 + 2) * 132 + n] = v.z;
                Ks[(rb + k8 * 4 + 3) * 132 + n] = v.w;
            }
        }
        __syncthreads();
        float2 lacc[4][4];
#pragma unroll
        for (int i = 0; i < 4; i++)
#pragma unroll
            for (int p = 0; p < 4; p++) lacc[i][p] = make_float2(0.f, 0.f);
#pragma unroll 4
        for (int jd = 0; jd < 64; jd++) {
            float2 aa[4];
#pragma unroll
            for (int i = 0; i < 4; i++) {
                float a = Qs[(ty * 4 + i) * 68 + jd];
                aa[i] = make_float2(a, a);
            }
            float4 k0 = *reinterpret_cast<const float4 *>(Ks + jd * 132 + tx * 4);
            float4 k1 = *reinterpret_cast<const float4 *>(Ks + jd * 132 + 64 + tx * 4);
            float2 bb[4] = {make_float2(k0.x, k0.y), make_float2(k0.z, k0.w),
                            make_float2(k1.x, k1.y), make_float2(k1.z, k1.w)};
#pragma unroll
            for (int i = 0; i < 4; i++)
#pragma unroll
                for (int p = 0; p < 4; p++) ffma2(lacc[i][p], aa[i], bb[p]);
        }
        __syncthreads();
#pragma unroll
        for (int i = 0; i < 4; i++) {
            float l[8] = {lacc[i][0].x, lacc[i][0].y, lacc[i][1].x, lacc[i][1].y,
                          lacc[i][2].x, lacc[i][2].y, lacc[i][3].x, lacc[i][3].y};
            float tm = l[0];
#pragma unroll
            for (int j = 1; j < 8; j++) tm = fmaxf(tm, l[j]);
            float nm = fmaxf(run_m[i], tm);
            float ssum = 0.f;
#pragma unroll
            for (int j = 0; j < 8; j++) ssum += fexp(l[j] - nm);
            run_s[i] = fmaf(run_s[i], fexp(run_m[i] - nm), ssum);
            run_m[i] = nm;
        }
    }
#pragma unroll
    for (int i = 0; i < 4; i++) {
        redm[tx * 64 + ty * 4 + i] = run_m[i];
        reds[tx * 64 + ty * 4 + i] = run_s[i];
    }
    __syncthreads();
    if (t < 64) {
        float gm = -INFINITY;
#pragma unroll
        for (int p = 0; p < 16; p++) gm = fmaxf(gm, redm[p * 64 + t]);
        float gs = 0.f;
#pragma unroll
        for (int p = 0; p < 16; p++)
            gs += reds[p * 64 + t] * fexp(redm[p * 64 + t] - gm);
        g_m[bm0 + t] = gm;
        g_inv[bm0 + t] = 1.0f / gs;
    }
}

// =====================================================================
// Kernel 3: out[m][d0:d0+256] = sum_n softmax(l)[m][n] * x[n][d0:d0+256]
// CTA: (batch, 64-query tile, 256-wide D chunk); recompute logits per
// chunk, P in smem, both GEMMs f32x2 register-tiled.
// =====================================================================
__global__ void __launch_bounds__(256) k_pv(const float *__restrict__ x,
                                            float *__restrict__ out) {
    extern __shared__ float sm[];
    float *Qs = sm;               // [64][68]
    float *Ks = Qs + 64 * 68;     // [64 r][132 n]
    float *Ps = Ks + 64 * 132;    // [64 m][132 n]
    float *Xvs = Ps + 64 * 132;   // [128 n][260 d]
    const int t = threadIdx.x;
    const int ty = t >> 4, tx = t & 15;
    const int b = blockIdx.z;
    const int m0 = b * S_ + blockIdx.y * 64;  // global query row
    const int d0 = blockIdx.x * 256;
    const int kbase = b * S_;

#pragma unroll
    for (int i = 0; i < 4; i++) {
        int f = t + i * 256;
        int r = f >> 4, c4 = f & 15;
        float4 v = *reinterpret_cast<const float4 *>(
            g_xq + (size_t)(m0 + r) * R_ + c4 * 4);
        *reinterpret_cast<float4 *>(Qs + r * 68 + c4 * 4) = v;
    }
    float rm[4], ri[4];
#pragma unroll
    for (int i = 0; i < 4; i++) {
        rm[i] = g_m[m0 + ty * 4 + i];
        ri[i] = g_inv[m0 + ty * 4 + i];
    }
    float2 yacc[4][8];
#pragma unroll
    for (int i = 0; i < 4; i++)
#pragma unroll
        for (int c = 0; c < 8; c++) yacc[i][c] = make_float2(0.f, 0.f);

    for (int nb = 0; nb < 32; nb++) {
        const int n0 = kbase + nb * 128;
        {  // K tile transposed
            int n = t >> 1, rb = (t & 1) * 32;
            const float *src = g_xq + (size_t)(n0 + n) * R_ + rb;
#pragma unroll
            for (int k8 = 0; k8 < 8; k8++) {
                float4 v = *reinterpret_cast<const float4 *>(src + k8 * 4);
                Ks[(rb + k8 * 4 + 0) * 132 + n] = v.x;
                Ks[(rb + k8 * 4 + 1) * 132 + n] = v.y;
                Ks[(rb + k8 * 4 + 2) * 132 + n] = v.z;
                Ks[(rb + k8 * 4 + 3) * 132 + n] = v.w;
            }
        }
#pragma unroll 8
        for (int i2 = 0; i2 < 32; i2++) {  // V tile: 128x256 = 8192 float4
            int f = t + i2 * 256;
            int r = f >> 6, c4 = f & 63;
            float4 v = *reinterpret_cast<const float4 *>(
                x + (size_t)(n0 + r) * D_ + d0 + c4 * 4);
            *reinterpret_cast<float4 *>(Xvs + r * 260 + c4 * 4) = v;
        }
        __syncthreads();

        float2 lacc[4][4];
#pragma unroll
        for (int i = 0; i < 4; i++)
#pragma unroll
            for (int p = 0; p < 4; p++) lacc[i][p] = make_float2(0.f, 0.f);
#pragma unroll 4
        for (int jd = 0; jd < 64; jd++) {
            float2 aa[4];
#pragma unroll
            for (int i = 0; i < 4; i++) {
                float a = Qs[(ty * 4 + i) * 68 + jd];
                aa[i] = make_float2(a, a);
            }
            float4 k0 = *reinterpret_cast<const float4 *>(Ks + jd * 132 + tx * 4);
            float4 k1 = *reinterpret_cast<const float4 *>(Ks + jd * 132 + 64 + tx * 4);
            float2 bb[4] = {make_float2(k0.x, k0.y), make_float2(k0.z, k0.w),
                            make_float2(k1.x, k1.y), make_float2(k1.z, k1.w)};
#pragma unroll
            for (int i = 0; i < 4; i++)
#pragma unroll
                for (int p = 0; p < 4; p++) ffma2(lacc[i][p], aa[i], bb[p]);
        }
        // P = exp(l - max) * inv_sum  -> smem
#pragma unroll
        for (int i = 0; i < 4; i++) {
            float p0 = fexp(lacc[i][0].x - rm[i]) * ri[i];
            float p1 = fexp(lacc[i][0].y - rm[i]) * ri[i];
            float p2 = fexp(lacc[i][1].x - rm[i]) * ri[i];
            float p3 = fexp(lacc[i][1].y - rm[i]) * ri[i];
            float p4 = fexp(lacc[i][2].x - rm[i]) * ri[i];
            float p5 = fexp(lacc[i][2].y - rm[i]) * ri[i];
            float p6 = fexp(lacc[i][3].x - rm[i]) * ri[i];
            float p7 = fexp(lacc[i][3].y - rm[i]) * ri[i];
            float *dst = Ps + (ty * 4 + i) * 132 + tx * 4;
            *reinterpret_cast<float4 *>(dst) = make_float4(p0, p1, p2, p3);
            *reinterpret_cast<float4 *>(dst + 64) = make_float4(p4, p5, p6, p7);
        }
        __syncthreads();
        // Y += P @ Xv
#pragma unroll 2
        for (int k = 0; k < 128; k++) {
            float2 pp[4];
#pragma unroll
            for (int i = 0; i < 4; i++) {
                float p = Ps[(ty * 4 + i) * 132 + k];
                pp[i] = make_float2(p, p);
            }
            float4 xv[4];
#pragma unroll
            for (int c = 0; c < 4; c++)
                xv[c] = *reinterpret_cast<const float4 *>(Xvs + k * 260 + c * 64 + tx * 4);
#pragma unroll
            for (int i = 0; i < 4; i++)
#pragma unroll
                for (int c = 0; c < 4; c++) {
                    ffma2(yacc[i][2 * c], pp[i], make_float2(xv[c].x, xv[c].y));
                    ffma2(yacc[i][2 * c + 1], pp[i], make_float2(xv[c].z, xv[c].w));
                }
        }
        __syncthreads();
    }
#pragma unroll
    for (int i = 0; i < 4; i++)
#pragma unroll
        for (int c = 0; c < 4; c++) {
            float4 o = make_float4(yacc[i][2 * c].x, yacc[i][2 * c].y,
                                   yacc[i][2 * c + 1].x, yacc[i][2 * c + 1].y);
            *reinterpret_cast<float4 *>(
                out + (size_t)(m0 + ty * 4 + i) * D_ + d0 + c * 64 + tx * 4) = o;
        }
}

// =====================================================================
extern "C" void kernel_launch(void *const *d_in, const int *in_sizes, int n_in,
                              void *d_out, int out_size) {
    const float *x = (const float *)d_in[0];
    const float *Q = (const float *)d_in[1];
    float *out = (float *)d_out;

    const int SM1 = (128 * 68 + 64 * 68) * 4;                       // 52,224
    const int SM2 = (64 * 68 + 64 * 132 + 2 * 16 * 64) * 4;         // 59,392
    const int SM3 = (64 * 68 + 2 * 64 * 132 + 128 * 260) * 4;       // 218,112

    cudaFuncSetAttribute(k_proj, cudaFuncAttributeMaxDynamicSharedMemorySize, SM1);
    cudaFuncSetAttribute(k_stats, cudaFuncAttributeMaxDynamicSharedMemorySize, SM2);
    cudaFuncSetAttribute(k_pv, cudaFuncAttributeMaxDynamicSharedMemorySize, SM3);

    k_proj<<<(B_ * S_) / 128, 256, SM1>>>(x, Q);
    k_stats<<<(B_ * S_) / 64, 256, SM2>>>();
    k_pv<<<dim3(D_ / 256, S_ / 64, B_), 256, SM3>>>(x, out);
}

// round 2
// speedup vs baseline: 1.0022x; 1.0022x over previous
#include <cuda_runtime.h>
#include <math.h>

#define B_ 8
#define S_ 4096
#define D_ 1024
#define R_ 64

// ---------------- scratch (no allocations allowed) ----------------
__device__ __align__(16) float g_xq[B_ * S_ * R_];   // 8 MB: x @ (Q*scale), [B*S][64]
__device__ float g_m[B_ * S_];                        // row max of logits
__device__ float g_inv[B_ * S_];                      // 1 / row sum of exp

// ---------------- packed fp32x2 FMA (Blackwell) ----------------
__device__ __forceinline__ void ffma2(float2 &c, const float2 a, const float2 b) {
    asm("fma.rn.f32x2 %0, %1, %2, %0;"
        : "+l"(*reinterpret_cast<unsigned long long *>(&c))
        : "l"(*reinterpret_cast<const unsigned long long *>(&a)),
          "l"(*reinterpret_cast<const unsigned long long *>(&b)));
}

// ---------------- software exp (avoids MUFU bottleneck) ----------------
// valid for x <= 0 (softmax-shifted logits); ~1e-6 rel err
__device__ __forceinline__ float fexp(float x) {
    x = fmaxf(x, -87.0f);
    float y = x * 1.4426950408889634f;   // log2(e)
    float n = rintf(y);
    float f = y - n;
    float p = 1.3333558e-3f;
    p = fmaf(p, f, 9.6181291e-3f);
    p = fmaf(p, f, 5.5504109e-2f);
    p = fmaf(p, f, 2.4022651e-1f);
    p = fmaf(p, f, 6.9314718e-1f);
    p = fmaf(p, f, 1.0f);
    int e = (int)n;
    return p * __int_as_float((e + 127) << 23);
}

// =====================================================================
// Kernel 1: g_xq[row][r] = scale * sum_d x[row][d] * Q[d][r]
// CTA: 128 rows x 64 cols, 256 threads, thread tile 4m x 8r (4 f32x2)
// =====================================================================
__global__ void __launch_bounds__(256) k_proj(const float *__restrict__ x,
                                              const float *__restrict__ Q) {
    extern __shared__ float sm[];
    float *Xs = sm;              // [128][68]
    float *Qs = sm + 128 * 68;   // [64][68]
    const int t = threadIdx.x;
    const int row0 = blockIdx.x * 128;
    const int ty = t >> 3;  // 0..31 -> m = ty*4+i
    const int tx = t & 7;   // 0..7  -> r = tx*8+j

    float2 acc[4][4];
#pragma unroll
    for (int i = 0; i < 4; i++)
#pragma unroll
        for (int p = 0; p < 4; p++) acc[i][p] = make_float2(0.f, 0.f);

    for (int dc = 0; dc < 16; dc++) {
        const int d0 = dc * 64;
#pragma unroll
        for (int i = 0; i < 8; i++) {  // X tile: 128x64 = 2048 float4
            int f = t + i * 256;
            int r = f >> 4, c4 = f & 15;
            float4 v = *reinterpret_cast<const float4 *>(
                x + (size_t)(row0 + r) * D_ + d0 + c4 * 4);
            *reinterpret_cast<float4 *>(Xs + r * 68 + c4 * 4) = v;
        }
#pragma unroll
        for (int i = 0; i < 4; i++) {  // Q tile: 64x64 = 1024 float4
            int f = t + i * 256;
            int r = f >> 4, c4 = f & 15;
            float4 v = *reinterpret_cast<const float4 *>(
                Q + (size_t)(d0 + r) * R_ + c4 * 4);
            *reinterpret_cast<float4 *>(Qs + r * 68 + c4 * 4) = v;
        }
        __syncthreads();
#pragma unroll 4
        for (int dd = 0; dd < 64; dd++) {
            float2 aa[4];
#pragma unroll
            for (int i = 0; i < 4; i++) {
                float a = Xs[(ty * 4 + i) * 68 + dd];
                aa[i] = make_float2(a, a);
            }
            float4 q0 = *reinterpret_cast<const float4 *>(Qs + dd * 68 + tx * 8);
            float4 q1 = *reinterpret_cast<const float4 *>(Qs + dd * 68 + tx * 8 + 4);
            float2 bb[4] = {make_float2(q0.x, q0.y), make_float2(q0.z, q0.w),
                            make_float2(q1.x, q1.y), make_float2(q1.z, q1.w)};
#pragma unroll
            for (int i = 0; i < 4; i++)
#pragma unroll
                for (int p = 0; p < 4; p++) ffma2(acc[i][p], aa[i], bb[p]);
        }
        __syncthreads();
    }
    const float scale = 0.03125f;  // 1/sqrt(1024)
#pragma unroll
    for (int i = 0; i < 4; i++) {
        float *dst = g_xq + (size_t)(row0 + ty * 4 + i) * R_ + tx * 8;
        float4 o0 = make_float4(acc[i][0].x * scale, acc[i][0].y * scale,
                                acc[i][1].x * scale, acc[i][1].y * scale);
        float4 o1 = make_float4(acc[i][2].x * scale, acc[i][2].y * scale,
                                acc[i][3].x * scale, acc[i][3].y * scale);
        *reinterpret_cast<float4 *>(dst) = o0;
        *reinterpret_cast<float4 *>(dst + 4) = o1;
    }
}

// =====================================================================
// Kernel 2: per-row softmax stats (max, 1/sum) via online reduction.
// CTA: 64 query rows, loop over key tiles of 128; thread tile 4m x 8n.
// =====================================================================
__global__ void __launch_bounds__(256) k_stats() {
    extern __shared__ float sm[];
    float *Qs = sm;                 // [64][68]
    float *Ks = Qs + 64 * 68;       // [64 r][132 n]  (transposed)
    float *redm = Ks + 64 * 132;    // [16][64]
    float *reds = redm + 16 * 64;   // [16][64]
    const int t = threadIdx.x;
    const int ty = t >> 4, tx = t & 15;
    const int bm0 = blockIdx.x * 64;  // global query row base
    const int kbase = (bm0 >> 12) << 12;

#pragma unroll
    for (int i = 0; i < 4; i++) {
        int f = t + i * 256;
        int r = f >> 4, c4 = f & 15;
        float4 v = *reinterpret_cast<const float4 *>(
            g_xq + (size_t)(bm0 + r) * R_ + c4 * 4);
        *reinterpret_cast<float4 *>(Qs + r * 68 + c4 * 4) = v;
    }

    float run_m[4], run_s[4];
#pragma unroll
    for (int i = 0; i < 4; i++) { run_m[i] = -INFINITY; run_s[i] = 0.f; }

    for (int nb = 0; nb < 32; nb++) {
        const int n0 = kbase + nb * 128;
        {  // load K transposed: Ks[r][n]
            int n = t >> 1, rb = (t & 1) * 32;
            const float *src = g_xq + (size_t)(n0 + n) * R_ + rb;
#pragma unroll
            for (int k8 = 0; k8 < 8; k8++) {
                float4 v = *reinterpret_cast<const float4 *>(src + k8 * 4);
                Ks[(rb + k8 * 4 + 0) * 132 + n] = v.x;
                Ks[(rb + k8 * 4 + 1) * 132 + n] = v.y;
                Ks[(rb + k8 * 4 + 2) * 132 + n] = v.z;
                Ks[(rb + k8 * 4 + 3) * 132 + n] = v.w;
            }
        }
        __syncthreads();
        float2 lacc[4][4];
#pragma unroll
        for (int i = 0; i < 4; i++)
#pragma unroll
            for (int p = 0; p < 4; p++) lacc[i][p] = make_float2(0.f, 0.f);
#pragma unroll 4
        for (int jd = 0; jd < 64; jd++) {
            float2 aa[4];
#pragma unroll
            for (int i = 0; i < 4; i++) {
                float a = Qs[(ty * 4 + i) * 68 + jd];
                aa[i] = make_float2(a, a);
            }
            float4 k0 = *reinterpret_cast<const float4 *>(Ks + jd * 132 + tx * 4);
            float4 k1 = *reinterpret_cast<const float4 *>(Ks + jd * 132 + 64 + tx * 4);
            float2 bb[4] = {make_float2(k0.x, k0.y), make_float2(k0.z, k0.w),
                            make_float2(k1.x, k1.y), make_float2(k1.z, k1.w)};
#pragma unroll
            for (int i = 0; i < 4; i++)
#pragma unroll
                for (int p = 0; p < 4; p++) ffma2(lacc[i][p], aa[i], bb[p]);
        }
        __syncthreads();
#pragma unroll
        for (int i = 0; i < 4; i++) {
            float l[8] = {lacc[i][0].x, lacc[i][0].y, lacc[i][1].x, lacc[i][1].y,
                          lacc[i][2].x, lacc[i][2].y, lacc[i][3].x, lacc[i][3].y};
            float tm = l[0];
#pragma unroll
            for (int j = 1; j < 8; j++) tm = fmaxf(tm, l[j]);
            float nm = fmaxf(run_m[i], tm);
            float ssum = 0.f;
#pragma unroll
            for (int j = 0; j < 8; j++) ssum += fexp(l[j] - nm);
            run_s[i] = fmaf(run_s[i], fexp(run_m[i] - nm), ssum);
            run_m[i] = nm;
        }
    }
#pragma unroll
    for (int i = 0; i < 4; i++) {
        redm[tx * 64 + ty * 4 + i] = run_m[i];
        reds[tx * 64 + ty * 4 + i] = run_s[i];
    }
    __syncthreads();
    if (t < 64) {
        float gm = -INFINITY;
#pragma unroll
        for (int p = 0; p < 16; p++) gm = fmaxf(gm, redm[p * 64 + t]);
        float gs = 0.f;
#pragma unroll
        for (int p = 0; p < 16; p++)
            gs += reds[p * 64 + t] * fexp(redm[p * 64 + t] - gm);
        g_m[bm0 + t] = gm;
        g_inv[bm0 + t] = 1.0f / gs;
    }
}

// =====================================================================
// Kernel 3: out[m][d0:d0+256] = sum_n softmax(l)[m][n] * x[n][d0:d0+256]
// CTA: (batch, 64-query tile, 256-wide D chunk); recompute logits per
// chunk, P in smem, both GEMMs f32x2 register-tiled.
// =====================================================================
__global__ void __launch_bounds__(256) k_pv(const float *__restrict__ x,
                                            float *__restrict__ out) {
    extern __shared__ float sm[];
    float *Qs = sm;               // [64][68]
    float *Ks = Qs + 64 * 68;     // [64 r][132 n]
    float *Ps = Ks + 64 * 132;    // [64 m][132 n]
    float *Xvs = Ps + 64 * 132;   // [128 n][260 d]
    const int t = threadIdx.x;
    const int ty = t >> 4, tx = t & 15;
    const int b = blockIdx.z;
    const int m0 = b * S_ + blockIdx.y * 64;  // global query row
    const int d0 = blockIdx.x * 256;
    const int kbase = b * S_;

#pragma unroll
    for (int i = 0; i < 4; i++) {
        int f = t + i * 256;
        int r = f >> 4, c4 = f & 15;
        float4 v = *reinterpret_cast<const float4 *>(
            g_xq + (size_t)(m0 + r) * R_ + c4 * 4);
        *reinterpret_cast<float4 *>(Qs + r * 68 + c4 * 4) = v;
    }
    float rm[4], ri[4];
#pragma unroll
    for (int i = 0; i < 4; i++) {
        rm[i] = g_m[m0 + ty * 4 + i];
        ri[i] = g_inv[m0 + ty * 4 + i];
    }
    float2 yacc[4][8];
#pragma unroll
    for (int i = 0; i < 4; i++)
#pragma unroll
        for (int c = 0; c < 8; c++) yacc[i][c] = make_float2(0.f, 0.f);

    for (int nb = 0; nb < 32; nb++) {
        const int n0 = kbase + nb * 128;
        {  // K tile transposed
            int n = t >> 1, rb = (t & 1) * 32;
            const float *src = g_xq + (size_t)(n0 + n) * R_ + rb;
#pragma unroll
            for (int k8 = 0; k8 < 8; k8++) {
                float4 v = *reinterpret_cast<const float4 *>(src + k8 * 4);
                Ks[(rb + k8 * 4 + 0) * 132 + n] = v.x;
                Ks[(rb + k8 * 4 + 1) * 132 + n] = v.y;
                Ks[(rb + k8 * 4 + 2) * 132 + n] = v.z;
                Ks[(rb + k8 * 4 + 3) * 132 + n] = v.w;
            }
        }
#pragma unroll 8
        for (int i2 = 0; i2 < 32; i2++) {  // V tile: 128x256 = 8192 float4
            int f = t + i2 * 256;
            int r = f >> 6, c4 = f & 63;
            float4 v = *reinterpret_cast<const float4 *>(
                x + (size_t)(n0 + r) * D_ + d0 + c4 * 4);
            *reinterpret_cast<float4 *>(Xvs + r * 260 + c4 * 4) = v;
        }
        __syncthreads();

        float2 lacc[4][4];
#pragma unroll
        for (int i = 0; i < 4; i++)
#pragma unroll
            for (int p = 0; p < 4; p++) lacc[i][p] = make_float2(0.f, 0.f);
#pragma unroll 4
        for (int jd = 0; jd < 64; jd++) {
            float2 aa[4];
#pragma unroll
            for (int i = 0; i < 4; i++) {
                float a = Qs[(ty * 4 + i) * 68 + jd];
                aa[i] = make_float2(a, a);
            }
            float4 k0 = *reinterpret_cast<const float4 *>(Ks + jd * 132 + tx * 4);
            float4 k1 = *reinterpret_cast<const float4 *>(Ks + jd * 132 + 64 + tx * 4);
            float2 bb[4] = {make_float2(k0.x, k0.y), make_float2(k0.z, k0.w),
                            make_float2(k1.x, k1.y), make_float2(k1.z, k1.w)};
#pragma unroll
            for (int i = 0; i < 4; i++)
#pragma unroll
                for (int p = 0; p < 4; p++) ffma2(lacc[i][p], aa[i], bb[p]);
        }
        // P = exp(l - max) * inv_sum  -> smem
#pragma unroll
        for (int i = 0; i < 4; i++) {
            float p0 = fexp(lacc[i][0].x - rm[i]) * ri[i];
            float p1 = fexp(lacc[i][0].y - rm[i]) * ri[i];
            float p2 = fexp(lacc[i][1].x - rm[i]) * ri[i];
            float p3 = fexp(lacc[i][1].y - rm[i]) * ri[i];
            float p4 = fexp(lacc[i][2].x - rm[i]) * ri[i];
            float p5 = fexp(lacc[i][2].y - rm[i]) * ri[i];
            float p6 = fexp(lacc[i][3].x - rm[i]) * ri[i];
            float p7 = fexp(lacc[i][3].y - rm[i]) * ri[i];
            float *dst = Ps + (ty * 4 + i) * 132 + tx * 4;
            *reinterpret_cast<float4 *>(dst) = make_float4(p0, p1, p2, p3);
            *reinterpret_cast<float4 *>(dst + 64) = make_float4(p4, p5, p6, p7);
        }
        __syncthreads();
        // Y += P @ Xv
#pragma unroll 2
        for (int k = 0; k < 128; k++) {
            float2 pp[4];
#pragma unroll
            for (int i = 0; i < 4; i++) {
                float p = Ps[(ty * 4 + i) * 132 + k];
                pp[i] = make_float2(p, p);
            }
            float4 xv[4];
#pragma unroll
            for (int c = 0; c < 4; c++)
                xv[c] = *reinterpret_cast<const float4 *>(Xvs + k * 260 + c * 64 + tx * 4);
#pragma unroll
            for (int i = 0; i < 4; i++)
#pragma unroll
                for (int c = 0; c < 4; c++) {
                    ffma2(yacc[i][2 * c], pp[i], make_float2(xv[c].x, xv[c].y));
                    ffma2(yacc[i][2 * c + 1], pp[i], make_float2(xv[c].z, xv[c].w));
                }
        }
        __syncthreads();
    }
#pragma unroll
    for (int i = 0; i < 4; i++)
#pragma unroll
        for (int c = 0; c < 4; c++) {
            float4 o = make_float4(yacc[i][2 * c].x, yacc[i][2 * c].y,
                                   yacc[i][2 * c + 1].x, yacc[i][2 * c + 1].y);
            *reinterpret_cast<float4 *>(
                out + (size_t)(m0 + ty * 4 + i) * D_ + d0 + c * 64 + tx * 4) = o;
        }
}

// =====================================================================
extern "C" void kernel_launch(void *const *d_in, const int *in_sizes, int n_in,
                              void *d_out, int out_size) {
    const float *x = (const float *)d_in[0];
    const float *Q = (const float *)d_in[1];
    float *out = (float *)d_out;

    const int SM1 = (128 * 68 + 64 * 68) * 4;                       // 52,224
    const int SM2 = (64 * 68 + 64 * 132 + 2 * 16 * 64) * 4;         // 59,392
    const int SM3 = (64 * 68 + 2 * 64 * 132 + 128 * 260) * 4;       // 218,112

    cudaFuncSetAttribute(k_proj, cudaFuncAttributeMaxDynamicSharedMemorySize, SM1);
    cudaFuncSetAttribute(k_stats, cudaFuncAttributeMaxDynamicSharedMemorySize, SM2);
    cudaFuncSetAttribute(k_pv, cudaFuncAttributeMaxDynamicSharedMemorySize, SM3);

    k_proj<<<(B_ * S_) / 128, 256, SM1>>>(x, Q);
    k_stats<<<(B_ * S_) / 64, 256, SM2>>>();
    k_pv<<<dim3(D_ / 256, S_ / 64, B_), 256, SM3>>>(x, out);
}

// round 4
// speedup vs baseline: 3.0438x; 3.0372x over previous
#include <cuda_runtime.h>
#include <stdint.h>
#include <math.h>

#define B_ 8
#define S_ 4096
#define D_ 1024
#define R_ 64

// ---------------- scratch (no allocations allowed) ----------------
__device__ __align__(16) float g_xq[B_ * S_ * R_];     // 8 MB: rna_tf32(x @ Q / 32)
__device__ __align__(16) float g_xr[B_ * S_ * D_];     // 128 MB: rna_tf32(x)
__device__ float g_inv[B_ * S_];                        // 1 / sum_n exp(logit)

// ---------------- helpers ----------------
__device__ __forceinline__ uint32_t smem_u32(const void *p) {
    uint32_t a;
    asm("{ .reg .u64 t; cvta.to.shared.u64 t, %1; cvt.u32.u64 %0, t; }" : "=r"(a) : "l"(p));
    return a;
}
__device__ __forceinline__ float rna_tf32(float v) {
    float r;
    asm("cvt.rna.tf32.f32 %0, %1;" : "=f"(r) : "f"(v));
    return r;
}
__device__ __forceinline__ void ffma2(float2 &c, const float2 a, const float2 b) {
    asm("fma.rn.f32x2 %0, %1, %2, %0;"
        : "+l"(*reinterpret_cast<unsigned long long *>(&c))
        : "l"(*reinterpret_cast<const unsigned long long *>(&a)),
          "l"(*reinterpret_cast<const unsigned long long *>(&b)));
}
__device__ __forceinline__ void cpa16(uint32_t dst, const float *src) {
    asm volatile("cp.async.cg.shared.global [%0], [%1], 16;" :: "r"(dst), "l"(src));
}
#define CP_COMMIT() asm volatile("cp.async.commit_group;" ::: "memory")
#define CP_WAIT0()  asm volatile("cp.async.wait_group 0;" ::: "memory")

// tf32 tensor-core mma: D(16x8) += A(16x8) * B(8x8)
__device__ __forceinline__ void mma_tf32(float *d, const uint32_t *a, const uint32_t *b) {
    asm volatile(
        "mma.sync.aligned.m16n8k8.row.col.f32.tf32.tf32.f32 "
        "{%0,%1,%2,%3}, {%4,%5,%6,%7}, {%8,%9}, {%0,%1,%2,%3};"
        : "+f"(d[0]), "+f"(d[1]), "+f"(d[2]), "+f"(d[3])
        : "r"(a[0]), "r"(a[1]), "r"(a[2]), "r"(a[3]), "r"(b[0]), "r"(b[1]));
}

// ---------------- shared smem float offsets (k_main) ----------------
#define FO_XQQ 0          // [128][68]
#define FO_XQK0 8704      // [64][68]
#define FO_XQK1 13056
#define FO_PS 17408       // [128][68]
#define FO_XV0 26112      // [64][136]
#define FO_XV1 34816
#define SMM_MAIN (43520 * 4)
// stats: XQQ @0, XQK0/1 @8704/13056, red @17408 (4*128)
#define SMM_STATS (17920 * 4)

// tile loaders (cp.async). rows x 64 floats, src row stride 64, dst stride 68
__device__ __forceinline__ void ld_tile64(uint32_t sb, int fo, const float *src,
                                          int rows, int tid) {
    int total = rows * 16;
    for (int idx = tid; idx < total; idx += 256) {
        int r = idx >> 4, c4 = idx & 15;
        cpa16(sb + (uint32_t)(fo + r * 68 + c4 * 4) * 4u, src + r * 64 + c4 * 4);
    }
}
// Xv tile: 64 rows x 128 floats, src row stride D_, dst stride 136
__device__ __forceinline__ void ld_xvtile(uint32_t sb, int fo, const float *src, int tid) {
    for (int idx = tid; idx < 2048; idx += 256) {
        int r = idx >> 5, c4 = idx & 31;
        cpa16(sb + (uint32_t)(fo + r * 136 + c4 * 4) * 4u, src + (size_t)r * D_ + c4 * 4);
    }
}

// stage1: S[128x64] = XQq @ XQk^T (K=64). warp grid 2Mx4N, warp tile 64x16.
__device__ __forceinline__ void stage1(const float *sm, int xqk_fo, int m0, int n0s,
                                       int g, int tg, float sacc[4][2][4]) {
    const float *XQ = sm + FO_XQQ;
    const float *XK = sm + xqk_fo;
#pragma unroll
    for (int k8 = 0; k8 < 8; k8++) {
        uint32_t a[4][4], bf[2][2];
        const int c = k8 * 8 + tg;
#pragma unroll
        for (int mi = 0; mi < 4; mi++) {
            int r = m0 + mi * 16 + g;
            a[mi][0] = __float_as_uint(XQ[r * 68 + c]);
            a[mi][1] = __float_as_uint(XQ[(r + 8) * 68 + c]);
            a[mi][2] = __float_as_uint(XQ[r * 68 + c + 4]);
            a[mi][3] = __float_as_uint(XQ[(r + 8) * 68 + c + 4]);
        }
#pragma unroll
        for (int ni = 0; ni < 2; ni++) {
            int n = n0s + ni * 8 + g;
            bf[ni][0] = __float_as_uint(XK[n * 68 + c]);
            bf[ni][1] = __float_as_uint(XK[n * 68 + c + 4]);
        }
#pragma unroll
        for (int mi = 0; mi < 4; mi++)
#pragma unroll
            for (int ni = 0; ni < 2; ni++) mma_tf32(sacc[mi][ni], a[mi], bf[ni]);
    }
}

// =====================================================================
// Kernel 1: g_xq = rna_tf32( (x @ Q) / 32 )  (FFMA2, proven)
// =====================================================================
__global__ void __launch_bounds__(256) k_proj(const float *__restrict__ x,
                                              const float *__restrict__ Q) {
    extern __shared__ float sm[];
    float *Xs = sm;
    float *Qs = sm + 128 * 68;
    const int t = threadIdx.x;
    const int row0 = blockIdx.x * 128;
    const int ty = t >> 3, tx = t & 7;

    float2 acc[4][4];
#pragma unroll
    for (int i = 0; i < 4; i++)
#pragma unroll
        for (int p = 0; p < 4; p++) acc[i][p] = make_float2(0.f, 0.f);

    for (int dc = 0; dc < 16; dc++) {
        const int d0 = dc * 64;
#pragma unroll
        for (int i = 0; i < 8; i++) {
            int f = t + i * 256;
            int r = f >> 4, c4 = f & 15;
            float4 v = *reinterpret_cast<const float4 *>(x + (size_t)(row0 + r) * D_ + d0 + c4 * 4);
            *reinterpret_cast<float4 *>(Xs + r * 68 + c4 * 4) = v;
        }
#pragma unroll
        for (int i = 0; i < 4; i++) {
            int f = t + i * 256;
            int r = f >> 4, c4 = f & 15;
            float4 v = *reinterpret_cast<const float4 *>(Q + (size_t)(d0 + r) * R_ + c4 * 4);
            *reinterpret_cast<float4 *>(Qs + r * 68 + c4 * 4) = v;
        }
        __syncthreads();
#pragma unroll 4
        for (int dd = 0; dd < 64; dd++) {
            float2 aa[4];
#pragma unroll
            for (int i = 0; i < 4; i++) {
                float a = Xs[(ty * 4 + i) * 68 + dd];
                aa[i] = make_float2(a, a);
            }
            float4 q0 = *reinterpret_cast<const float4 *>(Qs + dd * 68 + tx * 8);
            float4 q1 = *reinterpret_cast<const float4 *>(Qs + dd * 68 + tx * 8 + 4);
            float2 bb[4] = {make_float2(q0.x, q0.y), make_float2(q0.z, q0.w),
                            make_float2(q1.x, q1.y), make_float2(q1.z, q1.w)};
#pragma unroll
            for (int i = 0; i < 4; i++)
#pragma unroll
                for (int p = 0; p < 4; p++) ffma2(acc[i][p], aa[i], bb[p]);
        }
        __syncthreads();
    }
    const float scale = 0.03125f;
#pragma unroll
    for (int i = 0; i < 4; i++) {
        float *dst = g_xq + (size_t)(row0 + ty * 4 + i) * R_ + tx * 8;
        float4 o0 = make_float4(rna_tf32(acc[i][0].x * scale), rna_tf32(acc[i][0].y * scale),
                                rna_tf32(acc[i][1].x * scale), rna_tf32(acc[i][1].y * scale));
        float4 o1 = make_float4(rna_tf32(acc[i][2].x * scale), rna_tf32(acc[i][2].y * scale),
                                rna_tf32(acc[i][3].x * scale), rna_tf32(acc[i][3].y * scale));
        *reinterpret_cast<float4 *>(dst) = o0;
        *reinterpret_cast<float4 *>(dst + 4) = o1;
    }
}

// =====================================================================
// Kernel 2: g_xr = rna_tf32(x)   (unbiased tf32 rounding of V operand)
// =====================================================================
__global__ void __launch_bounds__(256) k_round(const float4 *__restrict__ x) {
    int i = blockIdx.x * 256 + threadIdx.x;
    float4 v = x[i];
    v.x = rna_tf32(v.x);
    v.y = rna_tf32(v.y);
    v.z = rna_tf32(v.z);
    v.w = rna_tf32(v.w);
    reinterpret_cast<float4 *>(g_xr)[i] = v;
}

// =====================================================================
// Kernel 3: stats — g_inv[row] = 1 / sum_n exp(logit[row][n])
// (logits bounded ~0.6, no max shift needed). Same stage1 mma as k_main.
// =====================================================================
__global__ void __launch_bounds__(256) k_stats() {
    extern __shared__ float sm[];
    const uint32_t sb = smem_u32(sm);
    const int tid = threadIdx.x, w = tid >> 5, lane = tid & 31;
    const int g = lane >> 2, tg = lane & 3;
    const int wm = w >> 2, wn = w & 3;
    const int m0 = wm * 64, n0s = wn * 16;
    const int q0 = blockIdx.x * 128;
    const int bb = q0 / S_;
    const float *xqq = g_xq + (size_t)q0 * R_;
    const float *xqk = g_xq + (size_t)bb * S_ * R_;

    ld_tile64(sb, FO_XQQ, xqq, 128, tid);
    ld_tile64(sb, FO_XQK0, xqk, 64, tid);
    CP_COMMIT();
    CP_WAIT0();
    __syncthreads();

    float rsum[4][2];
#pragma unroll
    for (int mi = 0; mi < 4; mi++) { rsum[mi][0] = 0.f; rsum[mi][1] = 0.f; }

    for (int kb = 0; kb < 64; kb++) {
        if (kb + 1 < 64) {
            ld_tile64(sb, ((kb + 1) & 1) ? FO_XQK1 : FO_XQK0,
                      xqk + (size_t)(kb + 1) * 64 * R_, 64, tid);
            CP_COMMIT();
        }
        float sacc[4][2][4];
#pragma unroll
        for (int mi = 0; mi < 4; mi++)
#pragma unroll
            for (int ni = 0; ni < 2; ni++)
#pragma unroll
                for (int c = 0; c < 4; c++) sacc[mi][ni][c] = 0.f;
        stage1(sm, (kb & 1) ? FO_XQK1 : FO_XQK0, m0, n0s, g, tg, sacc);
#pragma unroll
        for (int mi = 0; mi < 4; mi++)
#pragma unroll
            for (int ni = 0; ni < 2; ni++) {
                rsum[mi][0] += __expf(sacc[mi][ni][0]) + __expf(sacc[mi][ni][1]);
                rsum[mi][1] += __expf(sacc[mi][ni][2]) + __expf(sacc[mi][ni][3]);
            }
        if (kb + 1 < 64) CP_WAIT0();
        __syncthreads();
    }
    // reduce over tg (lanes xor 1, 2)
#pragma unroll
    for (int off = 1; off <= 2; off <<= 1)
#pragma unroll
        for (int mi = 0; mi < 4; mi++) {
            rsum[mi][0] += __shfl_xor_sync(0xffffffffu, rsum[mi][0], off);
            rsum[mi][1] += __shfl_xor_sync(0xffffffffu, rsum[mi][1], off);
        }
    float *red = sm + FO_PS;  // 4 x 128
    if (tg == 0) {
#pragma unroll
        for (int mi = 0; mi < 4; mi++) {
            red[wn * 128 + m0 + mi * 16 + g] = rsum[mi][0];
            red[wn * 128 + m0 + mi * 16 + 8 + g] = rsum[mi][1];
        }
    }
    __syncthreads();
    if (tid < 128) {
        float s = red[tid] + red[128 + tid] + red[256 + tid] + red[384 + tid];
        g_inv[q0 + tid] = 1.0f / s;
    }
}

// =====================================================================
// Kernel 4: flash main. CTA = (q-block 128, d-chunk 128, batch).
// Y register-resident; S via stage1 mma; P (tf32) via smem; Y += P @ Xv.
// =====================================================================
__global__ void __launch_bounds__(256, 1) k_main(float *__restrict__ out) {
    extern __shared__ float sm[];
    const uint32_t sb = smem_u32(sm);
    const int tid = threadIdx.x, w = tid >> 5, lane = tid & 31;
    const int g = lane >> 2, tg = lane & 3;
    const int wm = w >> 2, wn = w & 3;
    const int m0 = wm * 64, n0s = wn * 16, n0 = wn * 32;
    const int b = blockIdx.z, q0 = blockIdx.x * 128, d0 = blockIdx.y * 128;

    const float *xqq = g_xq + ((size_t)b * S_ + q0) * R_;
    const float *xqk = g_xq + (size_t)b * S_ * R_;
    const float *xv = g_xr + (size_t)b * S_ * D_ + d0;

    ld_tile64(sb, FO_XQQ, xqq, 128, tid);
    ld_tile64(sb, FO_XQK0, xqk, 64, tid);
    ld_xvtile(sb, FO_XV0, xv, tid);
    CP_COMMIT();
    CP_WAIT0();
    __syncthreads();

    float ri[4][2];
#pragma unroll
    for (int mi = 0; mi < 4; mi++) {
        ri[mi][0] = g_inv[(size_t)b * S_ + q0 + m0 + mi * 16 + g];
        ri[mi][1] = g_inv[(size_t)b * S_ + q0 + m0 + mi * 16 + 8 + g];
    }

    float yacc[4][4][4];
#pragma unroll
    for (int mi = 0; mi < 4; mi++)
#pragma unroll
        for (int nj = 0; nj < 4; nj++)
#pragma unroll
            for (int c = 0; c < 4; c++) yacc[mi][nj][c] = 0.f;

    for (int kb = 0; kb < 64; kb++) {
        if (kb + 1 < 64) {
            int nb = (kb + 1) & 1;
            ld_tile64(sb, nb ? FO_XQK1 : FO_XQK0, xqk + (size_t)(kb + 1) * 64 * R_, 64, tid);
            ld_xvtile(sb, nb ? FO_XV1 : FO_XV0, xv + (size_t)(kb + 1) * 64 * D_, tid);
            CP_COMMIT();
        }
        // ---- stage1: logits ----
        float sacc[4][2][4];
#pragma unroll
        for (int mi = 0; mi < 4; mi++)
#pragma unroll
            for (int ni = 0; ni < 2; ni++)
#pragma unroll
                for (int c = 0; c < 4; c++) sacc[mi][ni][c] = 0.f;
        stage1(sm, (kb & 1) ? FO_XQK1 : FO_XQK0, m0, n0s, g, tg, sacc);

        // ---- P = rna_tf32(exp(S) * inv) -> smem ----
#pragma unroll
        for (int mi = 0; mi < 4; mi++)
#pragma unroll
            for (int ni = 0; ni < 2; ni++) {
                int r0 = m0 + mi * 16 + g;
                int cc = n0s + ni * 8 + 2 * tg;
                float2 p0 = make_float2(rna_tf32(__expf(sacc[mi][ni][0]) * ri[mi][0]),
                                        rna_tf32(__expf(sacc[mi][ni][1]) * ri[mi][0]));
                float2 p1 = make_float2(rna_tf32(__expf(sacc[mi][ni][2]) * ri[mi][1]),
                                        rna_tf32(__expf(sacc[mi][ni][3]) * ri[mi][1]));
                *reinterpret_cast<float2 *>(sm + FO_PS + r0 * 68 + cc) = p0;
                *reinterpret_cast<float2 *>(sm + FO_PS + (r0 + 8) * 68 + cc) = p1;
            }
        __syncthreads();

        // ---- stage2: Y += P @ Xv ----
        const float *PS = sm + FO_PS;
        const float *XV = sm + ((kb & 1) ? FO_XV1 : FO_XV0);
#pragma unroll
        for (int k8 = 0; k8 < 8; k8++) {
            uint32_t a[4][4], bf[4][2];
            const int c = k8 * 8 + tg;
#pragma unroll
            for (int mi = 0; mi < 4; mi++) {
                int r = m0 + mi * 16 + g;
                a[mi][0] = __float_as_uint(PS[r * 68 + c]);
                a[mi][1] = __float_as_uint(PS[(r + 8) * 68 + c]);
                a[mi][2] = __float_as_uint(PS[r * 68 + c + 4]);
                a[mi][3] = __float_as_uint(PS[(r + 8) * 68 + c + 4]);
            }
#pragma unroll
            for (int nj = 0; nj < 4; nj++) {
                int n = n0 + nj * 8 + g;
                bf[nj][0] = __float_as_uint(XV[(k8 * 8 + tg) * 136 + n]);
                bf[nj][1] = __float_as_uint(XV[(k8 * 8 + tg + 4) * 136 + n]);
            }
#pragma unroll
            for (int mi = 0; mi < 4; mi++)
#pragma unroll
                for (int nj = 0; nj < 4; nj++) mma_tf32(yacc[mi][nj], a[mi], bf[nj]);
        }
        if (kb + 1 < 64) CP_WAIT0();
        __syncthreads();
    }

    // ---- epilogue ----
#pragma unroll
    for (int mi = 0; mi < 4; mi++) {
        size_t rbase = ((size_t)b * S_ + q0 + m0 + mi * 16 + g) * D_ + d0 + n0 + 2 * tg;
#pragma unroll
        for (int nj = 0; nj < 4; nj++) {
            *reinterpret_cast<float2 *>(out + rbase + nj * 8) =
                make_float2(yacc[mi][nj][0], yacc[mi][nj][1]);
            *reinterpret_cast<float2 *>(out + rbase + nj * 8 + (size_t)8 * D_) =
                make_float2(yacc[mi][nj][2], yacc[mi][nj][3]);
        }
    }
}

// =====================================================================
extern "C" void kernel_launch(void *const *d_in, const int *in_sizes, int n_in,
                              void *d_out, int out_size) {
    const float *x = (const float *)d_in[0];
    const float *Q = (const float *)d_in[1];
    float *out = (float *)d_out;

    const int SM1 = (128 * 68 + 64 * 68) * 4;
    cudaFuncSetAttribute(k_proj, cudaFuncAttributeMaxDynamicSharedMemorySize, SM1);
    cudaFuncSetAttribute(k_stats, cudaFuncAttributeMaxDynamicSharedMemorySize, SMM_STATS);
    cudaFuncSetAttribute(k_main, cudaFuncAttributeMaxDynamicSharedMemorySize, SMM_MAIN);

    k_proj<<<(B_ * S_) / 128, 256, SM1>>>(x, Q);
    k_round<<<(B_ * S_ * D_) / 4 / 256, 256>>>((const float4 *)x);
    k_stats<<<(B_ * S_) / 128, 256, SMM_STATS>>>();
    k_main<<<dim3(S_ / 128, D_ / 128, B_), 256, SMM_MAIN>>>(out);
}

// round 5
// speedup vs baseline: 3.9056x; 1.2831x over previous
#include <cuda_runtime.h>
#include <stdint.h>
#include <math.h>

#define B_ 8
#define S_ 4096
#define D_ 1024
#define R_ 64

// ---------------- scratch (no allocations allowed) ----------------
__device__ __align__(16) float g_xq[B_ * S_ * R_];     // 8 MB: rna_tf32(x @ Q / 32)
__device__ __align__(16) float g_xr[B_ * S_ * D_];     // 128 MB: rna_tf32(x)
__device__ float g_inv[B_ * S_];                        // 1 / sum_n exp(logit)

// ---------------- helpers ----------------
__device__ __forceinline__ uint32_t smem_u32(const void *p) {
    uint32_t a;
    asm("{ .reg .u64 t; cvta.to.shared.u64 t, %1; cvt.u32.u64 %0, t; }" : "=r"(a) : "l"(p));
    return a;
}
__device__ __forceinline__ float rna_tf32(float v) {
    float r;
    asm("cvt.rna.tf32.f32 %0, %1;" : "=f"(r) : "f"(v));
    return r;
}
__device__ __forceinline__ void ffma2(float2 &c, const float2 a, const float2 b) {
    asm("fma.rn.f32x2 %0, %1, %2, %0;"
        : "+l"(*reinterpret_cast<unsigned long long *>(&c))
        : "l"(*reinterpret_cast<const unsigned long long *>(&a)),
          "l"(*reinterpret_cast<const unsigned long long *>(&b)));
}
__device__ __forceinline__ void cpa16(uint32_t dst, const float *src) {
    asm volatile("cp.async.cg.shared.global [%0], [%1], 16;" :: "r"(dst), "l"(src));
}
#define CP_COMMIT() asm volatile("cp.async.commit_group;" ::: "memory")
#define CP_WAIT0()  asm volatile("cp.async.wait_group 0;" ::: "memory")

// tf32 tensor-core mma: D(16x8) += A(16x8) * B(8x8)
__device__ __forceinline__ void mma_tf32(float *d, const uint32_t *a, const uint32_t *b) {
    asm volatile(
        "mma.sync.aligned.m16n8k8.row.col.f32.tf32.tf32.f32 "
        "{%0,%1,%2,%3}, {%4,%5,%6,%7}, {%8,%9}, {%0,%1,%2,%3};"
        : "+f"(d[0]), "+f"(d[1]), "+f"(d[2]), "+f"(d[3])
        : "r"(a[0]), "r"(a[1]), "r"(a[2]), "r"(a[3]), "r"(b[0]), "r"(b[1]));
}

// ---------------- k_main smem float offsets (d-chunk = 256) ----------------
#define FO_XQQ 0          // [128][68]
#define FO_XQK 8704       // [64][68]  (single buffer)
#define FO_PS 13056       // [128][68]
#define FO_XV0 21760      // [64][264]
#define FO_XV1 38656      // [64][264]
#define SMM_MAIN (55552 * 4)   // 222,208 B

// ---------------- k_stats smem float offsets ----------------
#define SO_XQQ 0
#define SO_XQK0 8704
#define SO_XQK1 13056
#define SO_RED 17408
#define SMM_STATS (17920 * 4)

// tile loaders (cp.async). rows x 64 floats, src row stride 64, dst stride 68
__device__ __forceinline__ void ld_tile64(uint32_t sb, int fo, const float *src,
                                          int rows, int tid) {
    int total = rows * 16;
    for (int idx = tid; idx < total; idx += 256) {
        int r = idx >> 4, c4 = idx & 15;
        cpa16(sb + (uint32_t)(fo + r * 68 + c4 * 4) * 4u, src + r * 64 + c4 * 4);
    }
}
// Xv tile: 64 rows x 256 floats, src row stride D_, dst stride 264
__device__ __forceinline__ void ld_xv256(uint32_t sb, int fo, const float *src, int tid) {
    for (int idx = tid; idx < 4096; idx += 256) {
        int r = idx >> 6, c4 = idx & 63;
        cpa16(sb + (uint32_t)(fo + r * 264 + c4 * 4) * 4u, src + (size_t)r * D_ + c4 * 4);
    }
}

// stage1: S[128x64] = XQq @ XQk^T (K=64). warp grid 2Mx4N, warp tile 64x16.
__device__ __forceinline__ void stage1(const float *XQ, const float *XK, int m0, int n0s,
                                       int g, int tg, float sacc[4][2][4]) {
#pragma unroll
    for (int k8 = 0; k8 < 8; k8++) {
        uint32_t a[4][4], bf[2][2];
        const int c = k8 * 8 + tg;
#pragma unroll
        for (int mi = 0; mi < 4; mi++) {
            int r = m0 + mi * 16 + g;
            a[mi][0] = __float_as_uint(XQ[r * 68 + c]);
            a[mi][1] = __float_as_uint(XQ[(r + 8) * 68 + c]);
            a[mi][2] = __float_as_uint(XQ[r * 68 + c + 4]);
            a[mi][3] = __float_as_uint(XQ[(r + 8) * 68 + c + 4]);
        }
#pragma unroll
        for (int ni = 0; ni < 2; ni++) {
            int n = n0s + ni * 8 + g;
            bf[ni][0] = __float_as_uint(XK[n * 68 + c]);
            bf[ni][1] = __float_as_uint(XK[n * 68 + c + 4]);
        }
#pragma unroll
        for (int mi = 0; mi < 4; mi++)
#pragma unroll
            for (int ni = 0; ni < 2; ni++) mma_tf32(sacc[mi][ni], a[mi], bf[ni]);
    }
}

// =====================================================================
// Kernel 1: g_xq = rna_tf32( (x @ Q) / 32 )  (FFMA2, proven)
// =====================================================================
__global__ void __launch_bounds__(256) k_proj(const float *__restrict__ x,
                                              const float *__restrict__ Q) {
    extern __shared__ float sm[];
    float *Xs = sm;
    float *Qs = sm + 128 * 68;
    const int t = threadIdx.x;
    const int row0 = blockIdx.x * 128;
    const int ty = t >> 3, tx = t & 7;

    float2 acc[4][4];
#pragma unroll
    for (int i = 0; i < 4; i++)
#pragma unroll
        for (int p = 0; p < 4; p++) acc[i][p] = make_float2(0.f, 0.f);

    for (int dc = 0; dc < 16; dc++) {
        const int d0 = dc * 64;
#pragma unroll
        for (int i = 0; i < 8; i++) {
            int f = t + i * 256;
            int r = f >> 4, c4 = f & 15;
            float4 v = *reinterpret_cast<const float4 *>(x + (size_t)(row0 + r) * D_ + d0 + c4 * 4);
            *reinterpret_cast<float4 *>(Xs + r * 68 + c4 * 4) = v;
        }
#pragma unroll
        for (int i = 0; i < 4; i++) {
            int f = t + i * 256;
            int r = f >> 4, c4 = f & 15;
            float4 v = *reinterpret_cast<const float4 *>(Q + (size_t)(d0 + r) * R_ + c4 * 4);
            *reinterpret_cast<float4 *>(Qs + r * 68 + c4 * 4) = v;
        }
        __syncthreads();
#pragma unroll 4
        for (int dd = 0; dd < 64; dd++) {
            float2 aa[4];
#pragma unroll
            for (int i = 0; i < 4; i++) {
                float a = Xs[(ty * 4 + i) * 68 + dd];
                aa[i] = make_float2(a, a);
            }
            float4 q0 = *reinterpret_cast<const float4 *>(Qs + dd * 68 + tx * 8);
            float4 q1 = *reinterpret_cast<const float4 *>(Qs + dd * 68 + tx * 8 + 4);
            float2 bb[4] = {make_float2(q0.x, q0.y), make_float2(q0.z, q0.w),
                            make_float2(q1.x, q1.y), make_float2(q1.z, q1.w)};
#pragma unroll
            for (int i = 0; i < 4; i++)
#pragma unroll
                for (int p = 0; p < 4; p++) ffma2(acc[i][p], aa[i], bb[p]);
        }
        __syncthreads();
    }
    const float scale = 0.03125f;
#pragma unroll
    for (int i = 0; i < 4; i++) {
        float *dst = g_xq + (size_t)(row0 + ty * 4 + i) * R_ + tx * 8;
        float4 o0 = make_float4(rna_tf32(acc[i][0].x * scale), rna_tf32(acc[i][0].y * scale),
                                rna_tf32(acc[i][1].x * scale), rna_tf32(acc[i][1].y * scale));
        float4 o1 = make_float4(rna_tf32(acc[i][2].x * scale), rna_tf32(acc[i][2].y * scale),
                                rna_tf32(acc[i][3].x * scale), rna_tf32(acc[i][3].y * scale));
        *reinterpret_cast<float4 *>(dst) = o0;
        *reinterpret_cast<float4 *>(dst + 4) = o1;
    }
}

// =====================================================================
// Kernel 2: g_xr = rna_tf32(x)
// =====================================================================
__global__ void __launch_bounds__(256) k_round(const float4 *__restrict__ x) {
    int i = blockIdx.x * 256 + threadIdx.x;
    float4 v = x[i];
    v.x = rna_tf32(v.x);
    v.y = rna_tf32(v.y);
    v.z = rna_tf32(v.z);
    v.w = rna_tf32(v.w);
    reinterpret_cast<float4 *>(g_xr)[i] = v;
}

// =====================================================================
// Kernel 3: stats — g_inv[row] = 1 / sum_n exp(logit[row][n])
// (logits bounded; no max shift). Same stage1 mma order as k_main.
// =====================================================================
__global__ void __launch_bounds__(256) k_stats() {
    extern __shared__ float sm[];
    const uint32_t sb = smem_u32(sm);
    const int tid = threadIdx.x, w = tid >> 5, lane = tid & 31;
    const int g = lane >> 2, tg = lane & 3;
    const int wm = w >> 2, wn = w & 3;
    const int m0 = wm * 64, n0s = wn * 16;
    const int q0 = blockIdx.x * 128;
    const int bb = q0 / S_;
    const float *xqq = g_xq + (size_t)q0 * R_;
    const float *xqk = g_xq + (size_t)bb * S_ * R_;

    ld_tile64(sb, SO_XQQ, xqq, 128, tid);
    ld_tile64(sb, SO_XQK0, xqk, 64, tid);
    CP_COMMIT();
    CP_WAIT0();
    __syncthreads();

    float rsum[4][2];
#pragma unroll
    for (int mi = 0; mi < 4; mi++) { rsum[mi][0] = 0.f; rsum[mi][1] = 0.f; }

    for (int kb = 0; kb < 64; kb++) {
        if (kb + 1 < 64) {
            ld_tile64(sb, ((kb + 1) & 1) ? SO_XQK1 : SO_XQK0,
                      xqk + (size_t)(kb + 1) * 64 * R_, 64, tid);
            CP_COMMIT();
        }
        float sacc[4][2][4];
#pragma unroll
        for (int mi = 0; mi < 4; mi++)
#pragma unroll
            for (int ni = 0; ni < 2; ni++)
#pragma unroll
                for (int c = 0; c < 4; c++) sacc[mi][ni][c] = 0.f;
        stage1(sm + SO_XQQ, sm + ((kb & 1) ? SO_XQK1 : SO_XQK0), m0, n0s, g, tg, sacc);
#pragma unroll
        for (int mi = 0; mi < 4; mi++)
#pragma unroll
            for (int ni = 0; ni < 2; ni++) {
                rsum[mi][0] += __expf(sacc[mi][ni][0]) + __expf(sacc[mi][ni][1]);
                rsum[mi][1] += __expf(sacc[mi][ni][2]) + __expf(sacc[mi][ni][3]);
            }
        if (kb + 1 < 64) CP_WAIT0();
        __syncthreads();
    }
#pragma unroll
    for (int off = 1; off <= 2; off <<= 1)
#pragma unroll
        for (int mi = 0; mi < 4; mi++) {
            rsum[mi][0] += __shfl_xor_sync(0xffffffffu, rsum[mi][0], off);
            rsum[mi][1] += __shfl_xor_sync(0xffffffffu, rsum[mi][1], off);
        }
    float *red = sm + SO_RED;  // 4 x 128
    if (tg == 0) {
#pragma unroll
        for (int mi = 0; mi < 4; mi++) {
            red[wn * 128 + m0 + mi * 16 + g] = rsum[mi][0];
            red[wn * 128 + m0 + mi * 16 + 8 + g] = rsum[mi][1];
        }
    }
    __syncthreads();
    if (tid < 128) {
        float s = red[tid] + red[128 + tid] + red[256 + tid] + red[384 + tid];
        g_inv[q0 + tid] = 1.0f / s;
    }
}

// =====================================================================
// Kernel 4: flash main. CTA = (q-block 128, d-chunk 256, batch).
// Y register-resident (warp tile 64x64); stage1 mma -> P (tf32) -> stage2 mma.
// =====================================================================
__global__ void __launch_bounds__(256, 1) k_main(float *__restrict__ out) {
    extern __shared__ float sm[];
    const uint32_t sb = smem_u32(sm);
    const int tid = threadIdx.x, w = tid >> 5, lane = tid & 31;
    const int g = lane >> 2, tg = lane & 3;
    const int wm = w >> 2, wn = w & 3;
    const int m0 = wm * 64, n0s = wn * 16, n0 = wn * 64;
    const int b = blockIdx.z, q0 = blockIdx.x * 128, d0 = blockIdx.y * 256;

    const float *xqq = g_xq + ((size_t)b * S_ + q0) * R_;
    const float *xqk = g_xq + (size_t)b * S_ * R_;
    const float *xv = g_xr + (size_t)b * S_ * D_ + d0;

    ld_tile64(sb, FO_XQQ, xqq, 128, tid);
    ld_tile64(sb, FO_XQK, xqk, 64, tid);
    ld_xv256(sb, FO_XV0, xv, tid);
    CP_COMMIT();
    CP_WAIT0();
    __syncthreads();

    float ri[4][2];
#pragma unroll
    for (int mi = 0; mi < 4; mi++) {
        ri[mi][0] = g_inv[(size_t)b * S_ + q0 + m0 + mi * 16 + g];
        ri[mi][1] = g_inv[(size_t)b * S_ + q0 + m0 + mi * 16 + 8 + g];
    }

    float yacc[4][8][4];
#pragma unroll
    for (int mi = 0; mi < 4; mi++)
#pragma unroll
        for (int nj = 0; nj < 8; nj++)
#pragma unroll
            for (int c = 0; c < 4; c++) yacc[mi][nj][c] = 0.f;

    for (int kb = 0; kb < 64; kb++) {
        // ---- stage1: logits (reads XQK single buffer) ----
        float sacc[4][2][4];
#pragma unroll
        for (int mi = 0; mi < 4; mi++)
#pragma unroll
            for (int ni = 0; ni < 2; ni++)
#pragma unroll
                for (int c = 0; c < 4; c++) sacc[mi][ni][c] = 0.f;
        stage1(sm + FO_XQQ, sm + FO_XQK, m0, n0s, g, tg, sacc);

        // ---- P = rna_tf32(exp(S) * inv) -> smem ----
#pragma unroll
        for (int mi = 0; mi < 4; mi++)
#pragma unroll
            for (int ni = 0; ni < 2; ni++) {
                int r0 = m0 + mi * 16 + g;
                int cc = n0s + ni * 8 + 2 * tg;
                float2 p0 = make_float2(rna_tf32(__expf(sacc[mi][ni][0]) * ri[mi][0]),
                                        rna_tf32(__expf(sacc[mi][ni][1]) * ri[mi][0]));
                float2 p1 = make_float2(rna_tf32(__expf(sacc[mi][ni][2]) * ri[mi][1]),
                                        rna_tf32(__expf(sacc[mi][ni][3]) * ri[mi][1]));
                *reinterpret_cast<float2 *>(sm + FO_PS + r0 * 68 + cc) = p0;
                *reinterpret_cast<float2 *>(sm + FO_PS + (r0 + 8) * 68 + cc) = p1;
            }
        __syncthreads();  // stage1 done everywhere; P visible; prev stage2 done

        // ---- prefetch kb+1 (XQK safe: consumed; XV alt buffer: consumed in kb-1) ----
        if (kb + 1 < 64) {
            ld_tile64(sb, FO_XQK, xqk + (size_t)(kb + 1) * 64 * R_, 64, tid);
            ld_xv256(sb, ((kb + 1) & 1) ? FO_XV1 : FO_XV0,
                     xv + (size_t)(kb + 1) * 64 * D_, tid);
            CP_COMMIT();
        }

        // ---- stage2: Y += P @ Xv (warp tile 64x64) ----
        const float *PS = sm + FO_PS;
        const float *XV = sm + ((kb & 1) ? FO_XV1 : FO_XV0);
#pragma unroll
        for (int k8 = 0; k8 < 8; k8++) {
            uint32_t a[4][4], bf[8][2];
            const int c = k8 * 8 + tg;
#pragma unroll
            for (int mi = 0; mi < 4; mi++) {
                int r = m0 + mi * 16 + g;
                a[mi][0] = __float_as_uint(PS[r * 68 + c]);
                a[mi][1] = __float_as_uint(PS[(r + 8) * 68 + c]);
                a[mi][2] = __float_as_uint(PS[r * 68 + c + 4]);
                a[mi][3] = __float_as_uint(PS[(r + 8) * 68 + c + 4]);
            }
#pragma unroll
            for (int nj = 0; nj < 8; nj++) {
                int n = n0 + nj * 8 + g;
                bf[nj][0] = __float_as_uint(XV[(k8 * 8 + tg) * 264 + n]);
                bf[nj][1] = __float_as_uint(XV[(k8 * 8 + tg + 4) * 264 + n]);
            }
#pragma unroll
            for (int mi = 0; mi < 4; mi++)
#pragma unroll
                for (int nj = 0; nj < 8; nj++) mma_tf32(yacc[mi][nj], a[mi], bf[nj]);
        }
        if (kb + 1 < 64) CP_WAIT0();
        __syncthreads();
    }

    // ---- epilogue ----
#pragma unroll
    for (int mi = 0; mi < 4; mi++) {
        size_t rbase = ((size_t)b * S_ + q0 + m0 + mi * 16 + g) * D_ + d0 + n0 + 2 * tg;
#pragma unroll
        for (int nj = 0; nj < 8; nj++) {
            *reinterpret_cast<float2 *>(out + rbase + nj * 8) =
                make_float2(yacc[mi][nj][0], yacc[mi][nj][1]);
            *reinterpret_cast<float2 *>(out + rbase + nj * 8 + (size_t)8 * D_) =
                make_float2(yacc[mi][nj][2], yacc[mi][nj][3]);
        }
    }
}

// =====================================================================
extern "C" void kernel_launch(void *const *d_in, const int *in_sizes, int n_in,
                              void *d_out, int out_size) {
    const float *x = (const float *)d_in[0];
    const float *Q = (const float *)d_in[1];
    float *out = (float *)d_out;

    const int SM1 = (128 * 68 + 64 * 68) * 4;
    cudaFuncSetAttribute(k_proj, cudaFuncAttributeMaxDynamicSharedMemorySize, SM1);
    cudaFuncSetAttribute(k_stats, cudaFuncAttributeMaxDynamicSharedMemorySize, SMM_STATS);
    cudaFuncSetAttribute(k_main, cudaFuncAttributeMaxDynamicSharedMemorySize, SMM_MAIN);

    k_proj<<<(B_ * S_) / 128, 256, SM1>>>(x, Q);
    k_round<<<(B_ * S_ * D_) / 4 / 256, 256>>>((const float4 *)x);
    k_stats<<<(B_ * S_) / 128, 256, SMM_STATS>>>();
    k_main<<<dim3(S_ / 128, D_ / 256, B_), 256, SMM_MAIN>>>(out);
}

// round 6
// speedup vs baseline: 6.5513x; 1.6774x over previous
#include <cuda_runtime.h>
#include <cuda_fp16.h>
#include <stdint.h>
#include <math.h>

#define B_ 8
#define S_ 4096
#define D_ 1024
#define R_ 64

// ---------------- scratch (no allocations allowed) ----------------
__device__ __align__(16) __half g_xqh[B_ * S_ * R_];   // 4 MB: fp16(x @ Q / 32)
__device__ __align__(16) __half g_xTh[B_ * D_ * S_];   // 64 MB: fp16(x)^T [B][D][S]
__device__ float g_inv[B_ * S_];                        // 1 / sum_n exp(logit)

// ---------------- helpers ----------------
__device__ __forceinline__ uint32_t smem_u32(const void *p) {
    uint32_t a;
    asm("{ .reg .u64 t; cvta.to.shared.u64 t, %1; cvt.u32.u64 %0, t; }" : "=r"(a) : "l"(p));
    return a;
}
__device__ __forceinline__ void ffma2(float2 &c, const float2 a, const float2 b) {
    asm("fma.rn.f32x2 %0, %1, %2, %0;"
        : "+l"(*reinterpret_cast<unsigned long long *>(&c))
        : "l"(*reinterpret_cast<const unsigned long long *>(&a)),
          "l"(*reinterpret_cast<const unsigned long long *>(&b)));
}
__device__ __forceinline__ void cpa16(uint32_t dst, const void *src) {
    asm volatile("cp.async.cg.shared.global [%0], [%1], 16;" :: "r"(dst), "l"(src));
}
#define CP_COMMIT() asm volatile("cp.async.commit_group;" ::: "memory")
#define CP_WAIT0()  asm volatile("cp.async.wait_group 0;" ::: "memory")

// fp16 tensor-core mma: D(16x8,f32) += A(16x16,f16) * B(16x8,f16)
__device__ __forceinline__ void mma_f16(float *d, const uint32_t *a, const uint32_t *b) {
    asm volatile(
        "mma.sync.aligned.m16n8k16.row.col.f32.f16.f16.f32 "
        "{%0,%1,%2,%3}, {%4,%5,%6,%7}, {%8,%9}, {%0,%1,%2,%3};"
        : "+f"(d[0]), "+f"(d[1]), "+f"(d[2]), "+f"(d[3])
        : "r"(a[0]), "r"(a[1]), "r"(a[2]), "r"(a[3]), "r"(b[0]), "r"(b[1]));
}

// ---------------- k_main smem half offsets (row pad 72 halves) ----------------
#define HO_XQQ 0          // [128][72] h
#define HO_XQK 9216       // [64][72] h (single buffer)
#define HO_PS  13824      // [128][72] h
#define HO_XV0 23040      // [256][72] h (x^T: rows=d, cols=keys)
#define HO_XV1 41472
#define SMM_MAIN (59904 * 2)    // 119,808 B

// ---------------- k_stats smem ----------------
#define SO_XQQ 0
#define SO_XQK0 9216
#define SO_XQK1 13824
#define SO_REDB 36864     // byte offset of 512-float reduction area
#define SMM_STATS (36864 + 2048)

// tile loader: rows x 64 halves, row stride stride_h (halves), pad-72 dst
__device__ __forceinline__ void ld_tileh(uint32_t sb, int fo_h, const __half *src,
                                         size_t stride_h, int rows, int tid) {
    int total = rows * 8;
    for (int idx = tid; idx < total; idx += 256) {
        int r = idx >> 3, c8 = idx & 7;
        cpa16(sb + (uint32_t)(fo_h + r * 72 + c8 * 8) * 2u,
              src + (size_t)r * stride_h + c8 * 8);
    }
}

// stage1: S[128x64] = XQq @ XQk^T (K=64, 4 k16-steps). warp grid 2Mx4N.
__device__ __forceinline__ void stage1h(const __half *XQ, const __half *XK, int m0,
                                        int n0s, int g, int tg, float sacc[4][2][4]) {
#pragma unroll
    for (int kk = 0; kk < 4; kk++) {
        uint32_t a[4][4], bf[2][2];
        const int c = kk * 16 + 2 * tg;
#pragma unroll
        for (int mi = 0; mi < 4; mi++) {
            int r = m0 + mi * 16 + g;
            a[mi][0] = *reinterpret_cast<const uint32_t *>(XQ + r * 72 + c);
            a[mi][1] = *reinterpret_cast<const uint32_t *>(XQ + (r + 8) * 72 + c);
            a[mi][2] = *reinterpret_cast<const uint32_t *>(XQ + r * 72 + c + 8);
            a[mi][3] = *reinterpret_cast<const uint32_t *>(XQ + (r + 8) * 72 + c + 8);
        }
#pragma unroll
        for (int ni = 0; ni < 2; ni++) {
            int n = n0s + ni * 8 + g;
            bf[ni][0] = *reinterpret_cast<const uint32_t *>(XK + n * 72 + c);
            bf[ni][1] = *reinterpret_cast<const uint32_t *>(XK + n * 72 + c + 8);
        }
#pragma unroll
        for (int mi = 0; mi < 4; mi++)
#pragma unroll
            for (int ni = 0; ni < 2; ni++) mma_f16(sacc[mi][ni], a[mi], bf[ni]);
    }
}

// =====================================================================
// Kernel 1: g_xqh = fp16( (x @ Q) / 32 )  (FFMA2, proven)
// =====================================================================
__global__ void __launch_bounds__(256) k_proj(const float *__restrict__ x,
                                              const float *__restrict__ Q) {
    extern __shared__ float sm[];
    float *Xs = sm;
    float *Qs = sm + 128 * 68;
    const int t = threadIdx.x;
    const int row0 = blockIdx.x * 128;
    const int ty = t >> 3, tx = t & 7;

    float2 acc[4][4];
#pragma unroll
    for (int i = 0; i < 4; i++)
#pragma unroll
        for (int p = 0; p < 4; p++) acc[i][p] = make_float2(0.f, 0.f);

    for (int dc = 0; dc < 16; dc++) {
        const int d0 = dc * 64;
#pragma unroll
        for (int i = 0; i < 8; i++) {
            int f = t + i * 256;
            int r = f >> 4, c4 = f & 15;
            float4 v = *reinterpret_cast<const float4 *>(x + (size_t)(row0 + r) * D_ + d0 + c4 * 4);
            *reinterpret_cast<float4 *>(Xs + r * 68 + c4 * 4) = v;
        }
#pragma unroll
        for (int i = 0; i < 4; i++) {
            int f = t + i * 256;
            int r = f >> 4, c4 = f & 15;
            float4 v = *reinterpret_cast<const float4 *>(Q + (size_t)(d0 + r) * R_ + c4 * 4);
            *reinterpret_cast<float4 *>(Qs + r * 68 + c4 * 4) = v;
        }
        __syncthreads();
#pragma unroll 4
        for (int dd = 0; dd < 64; dd++) {
            float2 aa[4];
#pragma unroll
            for (int i = 0; i < 4; i++) {
                float a = Xs[(ty * 4 + i) * 68 + dd];
                aa[i] = make_float2(a, a);
            }
            float4 q0 = *reinterpret_cast<const float4 *>(Qs + dd * 68 + tx * 8);
            float4 q1 = *reinterpret_cast<const float4 *>(Qs + dd * 68 + tx * 8 + 4);
            float2 bb[4] = {make_float2(q0.x, q0.y), make_float2(q0.z, q0.w),
                            make_float2(q1.x, q1.y), make_float2(q1.z, q1.w)};
#pragma unroll
            for (int i = 0; i < 4; i++)
#pragma unroll
                for (int p = 0; p < 4; p++) ffma2(acc[i][p], aa[i], bb[p]);
        }
        __syncthreads();
    }
    const float scale = 0.03125f;
#pragma unroll
    for (int i = 0; i < 4; i++) {
        __half *dst = g_xqh + (size_t)(row0 + ty * 4 + i) * R_ + tx * 8;
        __half2 h0 = __floats2half2_rn(acc[i][0].x * scale, acc[i][0].y * scale);
        __half2 h1 = __floats2half2_rn(acc[i][1].x * scale, acc[i][1].y * scale);
        __half2 h2 = __floats2half2_rn(acc[i][2].x * scale, acc[i][2].y * scale);
        __half2 h3 = __floats2half2_rn(acc[i][3].x * scale, acc[i][3].y * scale);
        uint4 pk;
        pk.x = *reinterpret_cast<uint32_t *>(&h0);
        pk.y = *reinterpret_cast<uint32_t *>(&h1);
        pk.z = *reinterpret_cast<uint32_t *>(&h2);
        pk.w = *reinterpret_cast<uint32_t *>(&h3);
        *reinterpret_cast<uint4 *>(dst) = pk;
    }
}

// =====================================================================
// Kernel 2: g_xTh[b][d][s] = fp16( x[b][s][d] )   (tiled transpose)
// =====================================================================
__global__ void __launch_bounds__(256) k_tr(const float *__restrict__ x) {
    __shared__ float tile[32][33];
    const int b = blockIdx.z;
    const int s0 = blockIdx.x * 32;
    const int d0 = blockIdx.y * 32;
    const int tx = threadIdx.x & 31, ty = threadIdx.x >> 5;
    const float *src = x + ((size_t)b * S_ + s0) * D_ + d0;
#pragma unroll
    for (int i = 0; i < 4; i++) {
        int r = ty + i * 8;
        tile[r][tx] = src[(size_t)r * D_ + tx];
    }
    __syncthreads();
    __half *dst = g_xTh + ((size_t)b * D_ + d0) * S_ + s0;
#pragma unroll
    for (int i = 0; i < 4; i++) {
        int r = ty + i * 8;
        dst[(size_t)r * S_ + tx] = __float2half_rn(tile[tx][r]);
    }
}

// =====================================================================
// Kernel 3: stats — g_inv[row] = 1 / sum_n exp(logit[row][n])
// (logits bounded; no max shift). Same fp16 stage1 as k_main.
// =====================================================================
__global__ void __launch_bounds__(256) k_stats() {
    extern __shared__ char smc[];
    __half *smh = reinterpret_cast<__half *>(smc);
    const uint32_t sb = smem_u32(smc);
    const int tid = threadIdx.x, w = tid >> 5, lane = tid & 31;
    const int g = lane >> 2, tg = lane & 3;
    const int wm = w >> 2, wn = w & 3;
    const int m0 = wm * 64, n0s = wn * 16;
    const int q0 = blockIdx.x * 128;
    const int bb = q0 / S_;
    const __half *xqq = g_xqh + (size_t)q0 * R_;
    const __half *xqk = g_xqh + (size_t)bb * S_ * R_;

    ld_tileh(sb, SO_XQQ, xqq, R_, 128, tid);
    ld_tileh(sb, SO_XQK0, xqk, R_, 64, tid);
    CP_COMMIT();
    CP_WAIT0();
    __syncthreads();

    float rsum[4][2];
#pragma unroll
    for (int mi = 0; mi < 4; mi++) { rsum[mi][0] = 0.f; rsum[mi][1] = 0.f; }

    for (int kb = 0; kb < 64; kb++) {
        if (kb + 1 < 64) {
            ld_tileh(sb, ((kb + 1) & 1) ? SO_XQK1 : SO_XQK0,
                     xqk + (size_t)(kb + 1) * 64 * R_, R_, 64, tid);
            CP_COMMIT();
        }
        float sacc[4][2][4];
#pragma unroll
        for (int mi = 0; mi < 4; mi++)
#pragma unroll
            for (int ni = 0; ni < 2; ni++)
#pragma unroll
                for (int c = 0; c < 4; c++) sacc[mi][ni][c] = 0.f;
        stage1h(smh + SO_XQQ, smh + ((kb & 1) ? SO_XQK1 : SO_XQK0), m0, n0s, g, tg, sacc);
#pragma unroll
        for (int mi = 0; mi < 4; mi++)
#pragma unroll
            for (int ni = 0; ni < 2; ni++) {
                rsum[mi][0] += __expf(sacc[mi][ni][0]) + __expf(sacc[mi][ni][1]);
                rsum[mi][1] += __expf(sacc[mi][ni][2]) + __expf(sacc[mi][ni][3]);
            }
        if (kb + 1 < 64) CP_WAIT0();
        __syncthreads();
    }
#pragma unroll
    for (int off = 1; off <= 2; off <<= 1)
#pragma unroll
        for (int mi = 0; mi < 4; mi++) {
            rsum[mi][0] += __shfl_xor_sync(0xffffffffu, rsum[mi][0], off);
            rsum[mi][1] += __shfl_xor_sync(0xffffffffu, rsum[mi][1], off);
        }
    float *red = reinterpret_cast<float *>(smc + SO_REDB);  // 4 x 128
    if (tg == 0) {
#pragma unroll
        for (int mi = 0; mi < 4; mi++) {
            red[wn * 128 + m0 + mi * 16 + g] = rsum[mi][0];
            red[wn * 128 + m0 + mi * 16 + 8 + g] = rsum[mi][1];
        }
    }
    __syncthreads();
    if (tid < 128) {
        float s = red[tid] + red[128 + tid] + red[256 + tid] + red[384 + tid];
        g_inv[q0 + tid] = 1.0f / s;
    }
}

// =====================================================================
// Kernel 4: flash main (fp16 mma). CTA = (q-block 128, d-chunk 256, batch).
// Y register-resident f32 (warp tile 64x64); stage1 -> P(fp16) -> stage2.
// =====================================================================
__global__ void __launch_bounds__(256, 1) k_main(float *__restrict__ out) {
    extern __shared__ char smc[];
    __half *smh = reinterpret_cast<__half *>(smc);
    const uint32_t sb = smem_u32(smc);
    const int tid = threadIdx.x, w = tid >> 5, lane = tid & 31;
    const int g = lane >> 2, tg = lane & 3;
    const int wm = w >> 2, wn = w & 3;
    const int m0 = wm * 64, n0s = wn * 16, n0 = wn * 64;
    const int b = blockIdx.z, q0 = blockIdx.x * 128, d0 = blockIdx.y * 256;

    const __half *xqq = g_xqh + ((size_t)b * S_ + q0) * R_;
    const __half *xqk = g_xqh + (size_t)b * S_ * R_;
    const __half *xvt = g_xTh + ((size_t)b * D_ + d0) * S_;  // rows=d (256), cols=s

    ld_tileh(sb, HO_XQQ, xqq, R_, 128, tid);
    ld_tileh(sb, HO_XQK, xqk, R_, 64, tid);
    ld_tileh(sb, HO_XV0, xvt, S_, 256, tid);
    CP_COMMIT();
    CP_WAIT0();
    __syncthreads();

    float ri[4][2];
#pragma unroll
    for (int mi = 0; mi < 4; mi++) {
        ri[mi][0] = g_inv[(size_t)b * S_ + q0 + m0 + mi * 16 + g];
        ri[mi][1] = g_inv[(size_t)b * S_ + q0 + m0 + mi * 16 + 8 + g];
    }

    float yacc[4][8][4];
#pragma unroll
    for (int mi = 0; mi < 4; mi++)
#pragma unroll
        for (int nj = 0; nj < 8; nj++)
#pragma unroll
            for (int c = 0; c < 4; c++) yacc[mi][nj][c] = 0.f;

    for (int kb = 0; kb < 64; kb++) {
        // ---- stage1: logits ----
        float sacc[4][2][4];
#pragma unroll
        for (int mi = 0; mi < 4; mi++)
#pragma unroll
            for (int ni = 0; ni < 2; ni++)
#pragma unroll
                for (int c = 0; c < 4; c++) sacc[mi][ni][c] = 0.f;
        stage1h(smh + HO_XQQ, smh + HO_XQK, m0, n0s, g, tg, sacc);

        // ---- P = fp16(exp(S) * inv) -> smem ----
#pragma unroll
        for (int mi = 0; mi < 4; mi++)
#pragma unroll
            for (int ni = 0; ni < 2; ni++) {
                int r0 = m0 + mi * 16 + g;
                int cc = n0s + ni * 8 + 2 * tg;
                __half2 p0 = __floats2half2_rn(__expf(sacc[mi][ni][0]) * ri[mi][0],
                                               __expf(sacc[mi][ni][1]) * ri[mi][0]);
                __half2 p1 = __floats2half2_rn(__expf(sacc[mi][ni][2]) * ri[mi][1],
                                               __expf(sacc[mi][ni][3]) * ri[mi][1]);
                *reinterpret_cast<__half2 *>(smh + HO_PS + r0 * 72 + cc) = p0;
                *reinterpret_cast<__half2 *>(smh + HO_PS + (r0 + 8) * 72 + cc) = p1;
            }
        __syncthreads();  // stage1 everywhere done; P visible; prev stage2 done

        // ---- prefetch kb+1 ----
        if (kb + 1 < 64) {
            ld_tileh(sb, HO_XQK, xqk + (size_t)(kb + 1) * 64 * R_, R_, 64, tid);
            ld_tileh(sb, ((kb + 1) & 1) ? HO_XV1 : HO_XV0,
                     xvt + (size_t)(kb + 1) * 64, S_, 256, tid);
            CP_COMMIT();
        }

        // ---- stage2: Y += P @ XvT^T (warp tile 64x64, K=64, 4 k16-steps) ----
        const __half *PS = smh + HO_PS;
        const __half *XV = smh + ((kb & 1) ? HO_XV1 : HO_XV0);
#pragma unroll
        for (int kk = 0; kk < 4; kk++) {
            uint32_t a[4][4], bf[8][2];
            const int c = kk * 16 + 2 * tg;
#pragma unroll
            for (int mi = 0; mi < 4; mi++) {
                int r = m0 + mi * 16 + g;
                a[mi][0] = *reinterpret_cast<const uint32_t *>(PS + r * 72 + c);
                a[mi][1] = *reinterpret_cast<const uint32_t *>(PS + (r + 8) * 72 + c);
                a[mi][2] = *reinterpret_cast<const uint32_t *>(PS + r * 72 + c + 8);
                a[mi][3] = *reinterpret_cast<const uint32_t *>(PS + (r + 8) * 72 + c + 8);
            }
#pragma unroll
            for (int nj = 0; nj < 8; nj++) {
                int n = n0 + nj * 8 + g;
                bf[nj][0] = *reinterpret_cast<const uint32_t *>(XV + n * 72 + c);
                bf[nj][1] = *reinterpret_cast<const uint32_t *>(XV + n * 72 + c + 8);
            }
#pragma unroll
            for (int mi = 0; mi < 4; mi++)
#pragma unroll
                for (int nj = 0; nj < 8; nj++) mma_f16(yacc[mi][nj], a[mi], bf[nj]);
        }
        if (kb + 1 < 64) CP_WAIT0();
        __syncthreads();
    }

    // ---- epilogue ----
#pragma unroll
    for (int mi = 0; mi < 4; mi++) {
        size_t rbase = ((size_t)b * S_ + q0 + m0 + mi * 16 + g) * D_ + d0 + n0 + 2 * tg;
#pragma unroll
        for (int nj = 0; nj < 8; nj++) {
            *reinterpret_cast<float2 *>(out + rbase + nj * 8) =
                make_float2(yacc[mi][nj][0], yacc[mi][nj][1]);
            *reinterpret_cast<float2 *>(out + rbase + nj * 8 + (size_t)8 * D_) =
                make_float2(yacc[mi][nj][2], yacc[mi][nj][3]);
        }
    }
}

// =====================================================================
extern "C" void kernel_launch(void *const *d_in, const int *in_sizes, int n_in,
                              void *d_out, int out_size) {
    const float *x = (const float *)d_in[0];
    const float *Q = (const float *)d_in[1];
    float *out = (float *)d_out;

    const int SM1 = (128 * 68 + 64 * 68) * 4;
    cudaFuncSetAttribute(k_proj, cudaFuncAttributeMaxDynamicSharedMemorySize, SM1);
    cudaFuncSetAttribute(k_stats, cudaFuncAttributeMaxDynamicSharedMemorySize, SMM_STATS);
    cudaFuncSetAttribute(k_main, cudaFuncAttributeMaxDynamicSharedMemorySize, SMM_MAIN);

    k_proj<<<(B_ * S_) / 128, 256, SM1>>>(x, Q);
    k_tr<<<dim3(S_ / 32, D_ / 32, B_), 256>>>(x);
    k_stats<<<(B_ * S_) / 128, 256, SMM_STATS>>>();
    k_main<<<dim3(S_ / 128, D_ / 256, B_), 256, SMM_MAIN>>>(out);
}